// round 16
// baseline (speedup 1.0000x reference)
#include <cuda_runtime.h>

#define B_TOT   8192
#define T_IN    1024
#define T_OUT   1088               // 1024 + 64 free-running
#define EPB     8                  // elements per block (one warp)
#define THREADS 32                 // warp-autonomous block; lane = le*4 + sub
#define CHUNK   32
#define NCHUNK  (T_OUT / CHUNK)    // 34
#define XST     33                 // xbuf row stride floats (odd -> conflict-free)
#define YST     9                  // ybuf row stride floats (odd)

typedef unsigned long long ull;

__device__ __forceinline__ ull pk2(float lo, float hi) {
    ull r; asm("mov.b64 %0, {%1, %2};" : "=l"(r) : "f"(lo), "f"(hi)); return r;
}
__device__ __forceinline__ ull ffma2(ull a, ull b, ull c) {
    ull d; asm("fma.rn.f32x2 %0, %1, %2, %3;" : "=l"(d) : "l"(a), "l"(b), "l"(c)); return d;
}
__device__ __forceinline__ float2 unpk(ull v) {
    float lo, hi; asm("mov.b64 {%0, %1}, %2;" : "=f"(lo), "=f"(hi) : "l"(v));
    return make_float2(lo, hi);
}
__device__ __forceinline__ float tanh_fast(float x) {
    float y; asm("tanh.approx.f32 %0, %1;" : "=f"(y) : "f"(x)); return y;
}
// prescaled sigmoid: weights/biases already carry the 0.5 factor
__device__ __forceinline__ float sigp(float a) {
    return fmaf(tanh_fast(a), 0.5f, 0.5f);
}

// packed pair-row dot: 6 LDS.128, the 4 subs' slots adjacent (64B/warp-load
// -> 1 wavefront); 12 FFMA2 into one accumulator.
__device__ __forceinline__ void dotq(const ulonglong2* __restrict__ p,
                                     const ull* hh, ull& a) {
    #pragma unroll
    for (int jj = 0; jj < 6; jj++) {
        ulonglong2 v = p[jj * 4];
        a = ffma2(hh[2 * jj],     v.x, a);
        a = ffma2(hh[2 * jj + 1], v.y, a);
    }
}

__global__ __launch_bounds__(THREADS, 12)
void lstm_seq_kernel(const float* __restrict__ input,
                     const float* __restrict__ w_ih1, const float* __restrict__ w_hh1,
                     const float* __restrict__ b_ih1, const float* __restrict__ b_hh1,
                     const float* __restrict__ w_ih2, const float* __restrict__ w_hh2,
                     const float* __restrict__ b_ih2, const float* __restrict__ b_hh2,
                     const float* __restrict__ w_lin, const float* __restrict__ b_lin,
                     float* __restrict__ out)
{
    // sub-contiguous gate-packed PRESCALED weights (R9/R10 layout, verified):
    //   ull idx = pos*8 + sub*2 + t,  pos = (m*2+pair)*6 + jj,  j = 2*jj+t,
    //   u = sub*3 + m;  pair0 (i,f): rA=u, rB=12+u, sA=sB=0.5
    //                   pair1 (g,o): rA=24+u, rB=36+u, sA=1.0, sB=0.5
    __shared__ alignas(16) ull s_pk1[288], s_pki2[288], s_pkh2[288];
    __shared__ alignas(16) float xbuf[EPB * XST];
    __shared__ alignas(16) float ybuf[CHUNK * YST];

    const int tid = threadIdx.x;
    const int le  = tid >> 2;      // block-local element 0..7
    const int sub = tid & 3;       // unit group: owns units sub*3..sub*3+2
    const int u0  = sub * 3;

    // ---- stage packed prescaled weights ----
    for (int idx = tid; idx < 288; idx += THREADS) {
        const int t   = idx & 1;
        const int sb  = (idx >> 1) & 3;
        const int pos = idx >> 3;
        const int jj  = pos % 6;
        const int pp  = (pos / 6) & 1;
        const int m   = pos / 12;
        const int u   = sb * 3 + m;
        const int j   = 2 * jj + t;
        const int rA  = (pp ? 24 : 0) + u;
        const int rB  = (pp ? 36 : 12) + u;
        const float sA = pp ? 1.0f : 0.5f;
        s_pk1[idx]  = pk2(sA * w_hh1[rA * 12 + j], 0.5f * w_hh1[rB * 12 + j]);
        s_pki2[idx] = pk2(sA * w_ih2[rA * 12 + j], 0.5f * w_ih2[rB * 12 + j]);
        s_pkh2[idx] = pk2(sA * w_hh2[rA * 12 + j], 0.5f * w_hh2[rB * 12 + j]);
    }

    // per-thread packed constants (3 owned units), prescaled
    ull wx_if[3], wx_go[3], bz1_if[3], bz1_go[3], bz2_if[3], bz2_go[3];
    float wl[3];
    #pragma unroll
    for (int m = 0; m < 3; m++) {
        const int u = u0 + m;
        wx_if[m]  = pk2(0.5f * w_ih1[u],  0.5f * w_ih1[12 + u]);
        wx_go[m]  = pk2(w_ih1[24 + u],    0.5f * w_ih1[36 + u]);
        bz1_if[m] = pk2(0.5f * (b_ih1[u] + b_hh1[u]),
                        0.5f * (b_ih1[12 + u] + b_hh1[12 + u]));
        bz1_go[m] = pk2((b_ih1[24 + u] + b_hh1[24 + u]),
                        0.5f * (b_ih1[36 + u] + b_hh1[36 + u]));
        bz2_if[m] = pk2(0.5f * (b_ih2[u] + b_hh2[u]),
                        0.5f * (b_ih2[12 + u] + b_hh2[12 + u]));
        bz2_go[m] = pk2((b_ih2[24 + u] + b_hh2[24 + u]),
                        0.5f * (b_ih2[36 + u] + b_hh2[36 + u]));
        wl[m] = w_lin[u];
    }
    const float blin = b_lin[0];

    // state: h replicated as (h,h) packs, c private to owned units
    ull hh1[12], hh2[12];
    float c1[3], c2[3];
    #pragma unroll
    for (int j = 0; j < 12; j++) { hh1[j] = 0ULL; hh2[j] = 0ULL; }
    #pragma unroll
    for (int m = 0; m < 3; m++) { c1[m] = 0.0f; c2[m] = 0.0f; }

    const size_t eg0 = (size_t)blockIdx.x * EPB;
    const ulonglong2* p1  = (const ulonglong2*)s_pk1;
    const ulonglong2* pi2 = (const ulonglong2*)s_pki2;
    const ulonglong2* ph2 = (const ulonglong2*)s_pkh2;

    __syncwarp();   // weights staged (single warp)

    for (int ck = 0; ck < NCHUNK; ck++) {
        const int tbase = ck * CHUNK;

        // ---- stage x chunk: thread (le, sub) loads 2 float4 of its row ----
        {
            const float* src = input + (eg0 + le) * T_IN;
            float4 v0, v1;
            if (tbase < T_IN) {
                const float4* p = (const float4*)(src + tbase + sub * 8);
                v0 = p[0]; v1 = p[1];
            } else {
                const float xl = src[T_IN - 1];   // free-running: repeat last input
                v0 = make_float4(xl, xl, xl, xl); v1 = v0;
            }
            // transpose into xbuf[le*XST + t] layout via scalar stores
            float* xb = &xbuf[le * XST + sub * 8];
            xb[0] = v0.x; xb[1] = v0.y; xb[2] = v0.z; xb[3] = v0.w;
            xb[4] = v1.x; xb[5] = v1.y; xb[6] = v1.z; xb[7] = v1.w;
        }
        __syncwarp();

        #pragma unroll 1
        for (int i = 0; i < CHUNK; i++) {
            const float x = xbuf[le * XST + i];
            const ull xx = pk2(x, x);

            // ---------- layer 1 (3 owned units) ----------
            float h1n[3];
            #pragma unroll
            for (int m = 0; m < 3; m++) {
                ull aif = ffma2(xx, wx_if[m], bz1_if[m]);
                ull ago = ffma2(xx, wx_go[m], bz1_go[m]);
                dotq(p1 + (m * 2 + 0) * 24 + sub, hh1, aif);
                dotq(p1 + (m * 2 + 1) * 24 + sub, hh1, ago);
                float2 gif = unpk(aif), ggo = unpk(ago);
                float cc = fmaf(sigp(gif.y), c1[m], sigp(gif.x) * tanh_fast(ggo.x));
                c1[m] = cc;
                h1n[m] = sigp(ggo.y) * tanh_fast(cc);
            }
            // quad all-gather h1 (width-4 shuffles, no barrier)
            #pragma unroll
            for (int s = 0; s < 4; s++) {
                float a = __shfl_sync(0xffffffffu, h1n[0], s, 4);
                float b = __shfl_sync(0xffffffffu, h1n[1], s, 4);
                float c = __shfl_sync(0xffffffffu, h1n[2], s, 4);
                hh1[s * 3 + 0] = pk2(a, a);
                hh1[s * 3 + 1] = pk2(b, b);
                hh1[s * 3 + 2] = pk2(c, c);
            }

            // ---------- layer 2 ----------
            float h2n[3];
            #pragma unroll
            for (int m = 0; m < 3; m++) {
                ull aif = bz2_if[m];
                ull ago = bz2_go[m];
                dotq(pi2 + (m * 2 + 0) * 24 + sub, hh1, aif);
                dotq(pi2 + (m * 2 + 1) * 24 + sub, hh1, ago);
                dotq(ph2 + (m * 2 + 0) * 24 + sub, hh2, aif);
                dotq(ph2 + (m * 2 + 1) * 24 + sub, hh2, ago);
                float2 gif = unpk(aif), ggo = unpk(ago);
                float cc = fmaf(sigp(gif.y), c2[m], sigp(gif.x) * tanh_fast(ggo.x));
                c2[m] = cc;
                h2n[m] = sigp(ggo.y) * tanh_fast(cc);
            }
            // quad all-gather h2
            #pragma unroll
            for (int s = 0; s < 4; s++) {
                float a = __shfl_sync(0xffffffffu, h2n[0], s, 4);
                float b = __shfl_sync(0xffffffffu, h2n[1], s, 4);
                float c = __shfl_sync(0xffffffffu, h2n[2], s, 4);
                hh2[s * 3 + 0] = pk2(a, a);
                hh2[s * 3 + 1] = pk2(b, b);
                hh2[s * 3 + 2] = pk2(c, c);
            }

            // ---------- linear head + quad reduce ----------
            float yp = h2n[0] * wl[0] + h2n[1] * wl[1] + h2n[2] * wl[2];
            yp += __shfl_xor_sync(0xffffffffu, yp, 1, 4);
            yp += __shfl_xor_sync(0xffffffffu, yp, 2, 4);
            if (sub == 0) ybuf[i * YST + le] = yp + blin;
        }
        __syncwarp();

        // ---- drain y chunk to gmem (2 float4 per thread, coalesced per row) ----
        {
            const int t0 = sub * 8;
            float4 v0, v1;
            v0.x = ybuf[(t0 + 0) * YST + le];
            v0.y = ybuf[(t0 + 1) * YST + le];
            v0.z = ybuf[(t0 + 2) * YST + le];
            v0.w = ybuf[(t0 + 3) * YST + le];
            v1.x = ybuf[(t0 + 4) * YST + le];
            v1.y = ybuf[(t0 + 5) * YST + le];
            v1.z = ybuf[(t0 + 6) * YST + le];
            v1.w = ybuf[(t0 + 7) * YST + le];
            float4* p = (float4*)(out + (eg0 + le) * T_OUT + tbase + t0);
            p[0] = v0; p[1] = v1;
        }
        __syncwarp();
    }
}

extern "C" void kernel_launch(void* const* d_in, const int* in_sizes, int n_in,
                              void* d_out, int out_size) {
    // metadata order: input, future(int scalar), w_ih1, w_hh1, b_ih1, b_hh1,
    //                 w_ih2, w_hh2, b_ih2, b_hh2, w_lin, b_lin
    int base = (n_in >= 12 && in_sizes[1] == 1) ? 2 : 1;  // skip 'future' scalar if present
    const float* input = (const float*)d_in[0];
    const float* w_ih1 = (const float*)d_in[base + 0];
    const float* w_hh1 = (const float*)d_in[base + 1];
    const float* b_ih1 = (const float*)d_in[base + 2];
    const float* b_hh1 = (const float*)d_in[base + 3];
    const float* w_ih2 = (const float*)d_in[base + 4];
    const float* w_hh2 = (const float*)d_in[base + 5];
    const float* b_ih2 = (const float*)d_in[base + 6];
    const float* b_hh2 = (const float*)d_in[base + 7];
    const float* w_lin = (const float*)d_in[base + 8];
    const float* b_lin = (const float*)d_in[base + 9];

    lstm_seq_kernel<<<B_TOT / EPB, THREADS>>>(
        input, w_ih1, w_hh1, b_ih1, b_hh1,
        w_ih2, w_hh2, b_ih2, b_hh2, w_lin, b_lin,
        (float*)d_out);
}

// round 17
// speedup vs baseline: 1.2333x; 1.2333x over previous
#include <cuda_runtime.h>

#define B_TOT   8192
#define T_IN    1024
#define T_OUT   1088               // 1024 + 64 free-running
#define EPB     16                 // elements per block
#define THREADS 64                 // 2 warps; lane = le*4 + sub (4 threads/element)
#define CHUNK   32
#define NCHUNK  (T_OUT / CHUNK)    // 34
#define XST     17                 // xbuf/ybuf row stride floats (odd)
#define HROW    12                 // h row stride floats (48B, float4-aligned, conflict-free)

typedef unsigned long long ull;

__device__ __forceinline__ ull pk2(float lo, float hi) {
    ull r; asm("mov.b64 %0, {%1, %2};" : "=l"(r) : "f"(lo), "f"(hi)); return r;
}
__device__ __forceinline__ ull ffma2(ull a, ull b, ull c) {
    ull d; asm("fma.rn.f32x2 %0, %1, %2, %3;" : "=l"(d) : "l"(a), "l"(b), "l"(c)); return d;
}
__device__ __forceinline__ float2 unpk(ull v) {
    float lo, hi; asm("mov.b64 {%0, %1}, %2;" : "=f"(lo), "=f"(hi) : "l"(v));
    return make_float2(lo, hi);
}
__device__ __forceinline__ float tanh_fast(float x) {
    float y; asm("tanh.approx.f32 %0, %1;" : "=f"(y) : "f"(x)); return y;
}
// prescaled sigmoid: weights/biases already carry the 0.5 factor
__device__ __forceinline__ float sigp(float a) {
    return fmaf(tanh_fast(a), 0.5f, 0.5f);
}

// packed pair-row dot: 6 LDS.128, the 4 subs' slots adjacent (64B/warp span
// -> 1 wavefront); 12 FFMA2 into one accumulator.  (verified R9/R10/R16)
__device__ __forceinline__ void dotq(const ulonglong2* __restrict__ p,
                                     const ull* hh, ull& a) {
    #pragma unroll
    for (int jj = 0; jj < 6; jj++) {
        ulonglong2 v = p[jj * 4];
        a = ffma2(hh[2 * jj],     v.x, a);
        a = ffma2(hh[2 * jj + 1], v.y, a);
    }
}

// gather 12 floats of one h row (3 LDS.128) and replicate into (h,h) packs
__device__ __forceinline__ void gather_h(const float* __restrict__ row, ull* hh) {
    const float4* r = (const float4*)row;
    float4 A = r[0], B = r[1], C = r[2];
    hh[0] = pk2(A.x, A.x); hh[1]  = pk2(A.y, A.y);
    hh[2] = pk2(A.z, A.z); hh[3]  = pk2(A.w, A.w);
    hh[4] = pk2(B.x, B.x); hh[5]  = pk2(B.y, B.y);
    hh[6] = pk2(B.z, B.z); hh[7]  = pk2(B.w, B.w);
    hh[8] = pk2(C.x, C.x); hh[9]  = pk2(C.y, C.y);
    hh[10] = pk2(C.z, C.z); hh[11] = pk2(C.w, C.w);
}

__global__ __launch_bounds__(THREADS)
void lstm_seq_kernel(const float* __restrict__ input,
                     const float* __restrict__ w_ih1, const float* __restrict__ w_hh1,
                     const float* __restrict__ b_ih1, const float* __restrict__ b_hh1,
                     const float* __restrict__ w_ih2, const float* __restrict__ w_hh2,
                     const float* __restrict__ b_ih2, const float* __restrict__ b_hh2,
                     const float* __restrict__ w_lin, const float* __restrict__ b_lin,
                     float* __restrict__ out)
{
    // sub-contiguous gate-packed PRESCALED weights (R16 layout, passed):
    //   ull idx = pos*8 + sub*2 + t,  pos = (m*2+pair)*6 + jj,  j = 2*jj+t,
    //   u = sub*3 + m;  pair0 (i,f): rA=u, rB=12+u, scales (0.5, 0.5)
    //                   pair1 (g,o): rA=24+u, rB=36+u, scales (1.0, 0.5)
    __shared__ alignas(16) ull s_pk1[288], s_pki2[288], s_pkh2[288];
    __shared__ alignas(16) float xbuf[CHUNK * XST];
    __shared__ alignas(16) float ybuf[CHUNK * XST];
    __shared__ alignas(16) float h1buf[EPB * HROW];   // plain floats
    __shared__ alignas(16) float h2buf[EPB * HROW];

    const int tid = threadIdx.x;
    const int le  = tid >> 2;      // block-local element 0..15
    const int sub = tid & 3;       // unit group: owns units sub*3..sub*3+2
    const int u0  = sub * 3;

    // ---- stage packed prescaled weights (verbatim from R16, passed) ----
    for (int idx = tid; idx < 288; idx += THREADS) {
        const int t   = idx & 1;
        const int sb  = (idx >> 1) & 3;
        const int pos = idx >> 3;
        const int jj  = pos % 6;
        const int pp  = (pos / 6) & 1;
        const int m   = pos / 12;
        const int u   = sb * 3 + m;
        const int j   = 2 * jj + t;
        const int rA  = (pp ? 24 : 0) + u;
        const int rB  = (pp ? 36 : 12) + u;
        const float sA = pp ? 1.0f : 0.5f;
        s_pk1[idx]  = pk2(sA * w_hh1[rA * 12 + j], 0.5f * w_hh1[rB * 12 + j]);
        s_pki2[idx] = pk2(sA * w_ih2[rA * 12 + j], 0.5f * w_ih2[rB * 12 + j]);
        s_pkh2[idx] = pk2(sA * w_hh2[rA * 12 + j], 0.5f * w_hh2[rB * 12 + j]);
    }

    // per-thread packed constants (3 owned units), prescaled
    ull wx_if[3], wx_go[3], bz1_if[3], bz1_go[3], bz2_if[3], bz2_go[3];
    float wl[3];
    #pragma unroll
    for (int m = 0; m < 3; m++) {
        const int u = u0 + m;
        wx_if[m]  = pk2(0.5f * w_ih1[u],  0.5f * w_ih1[12 + u]);
        wx_go[m]  = pk2(w_ih1[24 + u],    0.5f * w_ih1[36 + u]);
        bz1_if[m] = pk2(0.5f * (b_ih1[u] + b_hh1[u]),
                        0.5f * (b_ih1[12 + u] + b_hh1[12 + u]));
        bz1_go[m] = pk2((b_ih1[24 + u] + b_hh1[24 + u]),
                        0.5f * (b_ih1[36 + u] + b_hh1[36 + u]));
        bz2_if[m] = pk2(0.5f * (b_ih2[u] + b_hh2[u]),
                        0.5f * (b_ih2[12 + u] + b_hh2[12 + u]));
        bz2_go[m] = pk2((b_ih2[24 + u] + b_hh2[24 + u]),
                        0.5f * (b_ih2[36 + u] + b_hh2[36 + u]));
        wl[m] = w_lin[u];
    }
    const float blin = b_lin[0];

    // state: h replicated as (h,h) packs in regs, c private to owned units
    ull hh1[12], hh2[12];
    float c1[3], c2[3];
    #pragma unroll
    for (int j = 0; j < 12; j++) { hh1[j] = 0ULL; hh2[j] = 0ULL; }
    #pragma unroll
    for (int m = 0; m < 3; m++) { c1[m] = 0.0f; c2[m] = 0.0f; }

    const size_t eg0 = (size_t)blockIdx.x * EPB;
    const ulonglong2* p1  = (const ulonglong2*)s_pk1;
    const ulonglong2* pi2 = (const ulonglong2*)s_pki2;
    const ulonglong2* ph2 = (const ulonglong2*)s_pkh2;

    __syncthreads();   // weights staged

    for (int ck = 0; ck < NCHUNK; ck++) {
        const int tbase = ck * CHUNK;

        // ---- stage x chunk: all 64 threads; thread (ee, half) loads 8 steps ----
        {
            const int ee = tid & 15, half = tid >> 4;     // half 0..3
            const float* src = input + (eg0 + ee) * T_IN;
            if (tbase < T_IN) {
                const float4* p = (const float4*)(src + tbase + half * 8);
                #pragma unroll
                for (int q = 0; q < 2; q++) {
                    float4 v = p[q];
                    const int t0 = half * 8 + q * 4;
                    xbuf[(t0 + 0) * XST + ee] = v.x;
                    xbuf[(t0 + 1) * XST + ee] = v.y;
                    xbuf[(t0 + 2) * XST + ee] = v.z;
                    xbuf[(t0 + 3) * XST + ee] = v.w;
                }
            } else {
                const float xl = src[T_IN - 1];   // free-running: repeat last input
                #pragma unroll
                for (int kk = 0; kk < 8; kk++)
                    xbuf[(half * 8 + kk) * XST + ee] = xl;
            }
        }
        __syncthreads();

        #pragma unroll 1
        for (int i = 0; i < CHUNK; i++) {
            const float x = xbuf[i * XST + le];
            const ull xx = pk2(x, x);

            // ---------- layer 1 (3 owned units) ----------
            float h1n[3];
            #pragma unroll
            for (int m = 0; m < 3; m++) {
                ull aif = ffma2(xx, wx_if[m], bz1_if[m]);
                ull ago = ffma2(xx, wx_go[m], bz1_go[m]);
                dotq(p1 + (m * 2 + 0) * 24 + sub, hh1, aif);
                dotq(p1 + (m * 2 + 1) * 24 + sub, hh1, ago);
                float2 gif = unpk(aif), ggo = unpk(ago);
                float cc = fmaf(sigp(gif.y), c1[m], sigp(gif.x) * tanh_fast(ggo.x));
                c1[m] = cc;
                h1n[m] = sigp(ggo.y) * tanh_fast(cc);
            }
            h1buf[le * HROW + u0 + 0] = h1n[0];
            h1buf[le * HROW + u0 + 1] = h1n[1];
            h1buf[le * HROW + u0 + 2] = h1n[2];
            __syncthreads();
            gather_h(&h1buf[le * HROW], hh1);

            // ---------- layer 2 ----------
            float h2n[3];
            #pragma unroll
            for (int m = 0; m < 3; m++) {
                ull aif = bz2_if[m];
                ull ago = bz2_go[m];
                dotq(pi2 + (m * 2 + 0) * 24 + sub, hh1, aif);
                dotq(pi2 + (m * 2 + 1) * 24 + sub, hh1, ago);
                dotq(ph2 + (m * 2 + 0) * 24 + sub, hh2, aif);
                dotq(ph2 + (m * 2 + 1) * 24 + sub, hh2, ago);
                float2 gif = unpk(aif), ggo = unpk(ago);
                float cc = fmaf(sigp(gif.y), c2[m], sigp(gif.x) * tanh_fast(ggo.x));
                c2[m] = cc;
                h2n[m] = sigp(ggo.y) * tanh_fast(cc);
            }
            h2buf[le * HROW + u0 + 0] = h2n[0];
            h2buf[le * HROW + u0 + 1] = h2n[1];
            h2buf[le * HROW + u0 + 2] = h2n[2];

            // ---------- linear head + quad reduce (no barrier needed) ----------
            float yp = h2n[0] * wl[0] + h2n[1] * wl[1] + h2n[2] * wl[2];
            yp += __shfl_xor_sync(0xffffffffu, yp, 1, 4);
            yp += __shfl_xor_sync(0xffffffffu, yp, 2, 4);
            if (sub == 0) ybuf[i * XST + le] = yp + blin;

            __syncthreads();
            gather_h(&h2buf[le * HROW], hh2);
        }
        // NOTE: last gather's barrier also ordered ybuf writes for the drain below

        // ---- drain y chunk to gmem (float4 stores) ----
        {
            const int ee = tid & 15, half = tid >> 4;
            #pragma unroll
            for (int q = 0; q < 2; q++) {
                const int t0 = half * 8 + q * 4;
                float4 v;
                v.x = ybuf[(t0 + 0) * XST + ee];
                v.y = ybuf[(t0 + 1) * XST + ee];
                v.z = ybuf[(t0 + 2) * XST + ee];
                v.w = ybuf[(t0 + 3) * XST + ee];
                *(float4*)(out + (eg0 + ee) * T_OUT + tbase + t0) = v;
            }
        }
        __syncthreads();   // protect xbuf/ybuf reuse next chunk
    }
}

extern "C" void kernel_launch(void* const* d_in, const int* in_sizes, int n_in,
                              void* d_out, int out_size) {
    // metadata order: input, future(int scalar), w_ih1, w_hh1, b_ih1, b_hh1,
    //                 w_ih2, w_hh2, b_ih2, b_hh2, w_lin, b_lin
    int base = (n_in >= 12 && in_sizes[1] == 1) ? 2 : 1;  // skip 'future' scalar if present
    const float* input = (const float*)d_in[0];
    const float* w_ih1 = (const float*)d_in[base + 0];
    const float* w_hh1 = (const float*)d_in[base + 1];
    const float* b_ih1 = (const float*)d_in[base + 2];
    const float* b_hh1 = (const float*)d_in[base + 3];
    const float* w_ih2 = (const float*)d_in[base + 4];
    const float* w_hh2 = (const float*)d_in[base + 5];
    const float* b_ih2 = (const float*)d_in[base + 6];
    const float* b_hh2 = (const float*)d_in[base + 7];
    const float* w_lin = (const float*)d_in[base + 8];
    const float* b_lin = (const float*)d_in[base + 9];

    lstm_seq_kernel<<<B_TOT / EPB, THREADS>>>(
        input, w_ih1, w_hh1, b_ih1, b_hh1,
        w_ih2, w_hh2, b_ih2, b_hh2, w_lin, b_lin,
        (float*)d_out);
}